// round 7
// baseline (speedup 1.0000x reference)
#include <cuda_runtime.h>
#include <cuda_fp16.h>
#include <cstdint>

// corr[b,n] = (1/16384) * sum_h EhT[n,h] * ( sum_w EwT[n,w] * act[b,h,w] )
// Single-pass fp16 warp-mma GEMM (m16n8k16.f16, fp32 accum), pipelined
// cp.async staging (2 K-chunks), EhT consumed from L2 in the epilogue.
// Per CTA (n-tile 128, batch b): M=128(n) x N=128(h) x K=128(w).

#define HDIM 128
#define NPTS 4096

__device__ __align__(256) __half g_A[NPTS * HDIM];       // EwT [n][w]
__device__ __align__(256) __half g_E[NPTS * HDIM];       // EhT [n][h] (unscaled)
__device__ __align__(256) __half g_act[8 * HDIM * HDIM]; // act [b][h][w]

// ---------------------------------------------------------------------------
__device__ __forceinline__ uint32_t smem_to_u32(const void* p) {
    uint32_t a;
    asm("{ .reg .u64 t; cvta.to.shared.u64 t, %1; cvt.u32.u64 %0, t; }" : "=r"(a) : "l"(p));
    return a;
}
#define CP16(dst, src) \
    asm volatile("cp.async.cg.shared.global [%0], [%1], 16;" :: "r"(dst), "l"(src) : "memory")
#define CP_COMMIT() asm volatile("cp.async.commit_group;" ::: "memory")
#define CP_WAIT(n)  asm volatile("cp.async.wait_group %0;" :: "n"(n) : "memory")

#define LDSM_X4(r0, r1, r2, r3, addr)                                          \
    asm volatile("ldmatrix.sync.aligned.m8n8.x4.shared.b16 {%0,%1,%2,%3}, [%4];" \
        : "=r"(r0), "=r"(r1), "=r"(r2), "=r"(r3) : "r"(addr))

#define MMA_F16(c, a, b0, b1)                                                  \
    asm volatile("mma.sync.aligned.m16n8k16.row.col.f32.f16.f16.f32 "           \
        "{%0,%1,%2,%3},{%4,%5,%6,%7},{%8,%9},{%0,%1,%2,%3};"                    \
        : "+f"((c)[0]), "+f"((c)[1]), "+f"((c)[2]), "+f"((c)[3])                \
        : "r"((a)[0]), "r"((a)[1]), "r"((a)[2]), "r"((a)[3]), "r"(b0), "r"(b1))

// ---------------------------------------------------------------------------
// Kernel 1: fp16 factor tables. idx -> (n = idx>>7, j = idx&127).
// ---------------------------------------------------------------------------
__global__ __launch_bounds__(256) void prep_kernel(
    const float* __restrict__ act, const float* __restrict__ mu,
    const float* __restrict__ sigma)
{
    const int idx = blockIdx.x * 256 + threadIdx.x;   // 0 .. 524287
    const int n = idx >> 7;
    const int j = idx & 127;
    const float g = (float)j * (1.0f / 128.0f);

    const float2 m = ((const float2*)mu)[n];
    const float2 s = ((const float2*)sigma)[n];

    const float dy = g - m.y;   // EwT[n][w]
    g_A[idx] = __float2half_rn(__expf(-(dy * dy / (2.0f * s.y * s.y))));
    const float dx = g - m.x;   // EhT[n][h] (scale applied in fp32 epilogue)
    g_E[idx] = __float2half_rn(__expf(-(dx * dx / (2.0f * s.x * s.x))));

    if (idx < 8 * HDIM * HDIM)
        g_act[idx] = __float2half_rn(act[idx]);
}

// ---------------------------------------------------------------------------
// Kernel 2. Grid (32 n-tiles, 8 b), 256 threads = 8 warps:
// wm = wid&3 (n blocks of 32), wn = wid>>2 (h halves of 64).
// Rows padded to 272B = 17*16 -> ldmatrix conflict-free ((17r+u) mod 8 = r+u).
// Staging pipelined: chunk0 = w[0:64) group, chunk1 = w[64:128) group.
// ---------------------------------------------------------------------------
#define NSTRIDE 272
#define TAB_BYTES (128 * NSTRIDE)             // 34816
#define SMEM_REQ  (2 * TAB_BYTES)             // 69632

__global__ __launch_bounds__(256) void corr_mma_kernel(float* __restrict__ out)
{
    extern __shared__ char smem[];
    const uint32_t sb = smem_to_u32(smem);
    const uint32_t sA = sb;                  // EwT [n][w]
    const uint32_t sB = sb + TAB_BYTES;      // act [h][w]

    const int tid = threadIdx.x;
    const int wid = tid >> 5, l = tid & 31;
    const int wm = wid & 3, wn = wid >> 2;
    const int b  = blockIdx.y;
    const int n0 = blockIdx.x * 128;

    const __half* gA = g_A + n0 * HDIM;
    const __half* gB = g_act + b * HDIM * HDIM;

    // Chunk 0: w columns [0,64)  (u 0..7)
    #pragma unroll
    for (int i = tid; i < 1024; i += 256) {
        const int r = i >> 3, u = i & 7;
        const uint32_t d = r * NSTRIDE + u * 16;
        const int so = r * HDIM + u * 8;
        CP16(sA + d, gA + so);
        CP16(sB + d, gB + so);
    }
    CP_COMMIT();
    // Chunk 1: w columns [64,128) (u 8..15)
    #pragma unroll
    for (int i = tid; i < 1024; i += 256) {
        const int r = i >> 3, u = (i & 7) + 8;
        const uint32_t d = r * NSTRIDE + u * 16;
        const int so = r * HDIM + u * 8;
        CP16(sA + d, gA + so);
        CP16(sB + d, gB + so);
    }
    CP_COMMIT();

    float acc[2][8][4];
    #pragma unroll
    for (int mt = 0; mt < 2; mt++)
        #pragma unroll
        for (int nt = 0; nt < 8; nt++)
            #pragma unroll
            for (int k = 0; k < 4; k++) acc[mt][nt][k] = 0.0f;

    const uint32_t lrow = l & 15, lcol = (l >> 4) * 16;
    const uint32_t aBase = sA + (wm * 32 + lrow) * NSTRIDE + lcol;
    const uint32_t bBase = sB + (wn * 64 + lrow) * NSTRIDE + lcol;

#define COMPUTE_KS(ks)                                                          \
    {                                                                           \
        const uint32_t koff = (ks) * 32;                                        \
        uint32_t ah[2][4], bb[4][4];                                            \
        _Pragma("unroll")                                                       \
        for (int mt = 0; mt < 2; mt++)                                          \
            LDSM_X4(ah[mt][0], ah[mt][1], ah[mt][2], ah[mt][3],                 \
                    aBase + mt * (16 * NSTRIDE) + koff);                        \
        _Pragma("unroll")                                                       \
        for (int p = 0; p < 4; p++)                                             \
            LDSM_X4(bb[p][0], bb[p][1], bb[p][2], bb[p][3],                     \
                    bBase + p * (16 * NSTRIDE) + koff);                         \
        _Pragma("unroll")                                                       \
        for (int mt = 0; mt < 2; mt++)                                          \
            _Pragma("unroll")                                                   \
            for (int p = 0; p < 4; p++) {                                       \
                MMA_F16(acc[mt][2 * p],     ah[mt], bb[p][0], bb[p][2]);        \
                MMA_F16(acc[mt][2 * p + 1], ah[mt], bb[p][1], bb[p][3]);        \
            }                                                                   \
    }

    // Compute chunk 0 while chunk 1 is still in flight.
    CP_WAIT(1);
    __syncthreads();
    #pragma unroll
    for (int ks = 0; ks < 4; ks++) COMPUTE_KS(ks);

    CP_WAIT(0);
    __syncthreads();
    #pragma unroll
    for (int ks = 4; ks < 8; ks++) COMPUTE_KS(ks);

    // Epilogue: thread's D rows = wm*32 + mt*16 + rh*8 + l/4 (n),
    // cols = wn*64 + nt*8 + 2(l&3)+{0,1} (h). EhT read from L2 (half2),
    // quad shuffle, then cross-(wn)-warp smem reduce.
    float rowsum[2][2];
    #pragma unroll
    for (int mt = 0; mt < 2; mt++)
        #pragma unroll
        for (int rh = 0; rh < 2; rh++) {
            const int nloc = wm * 32 + mt * 16 + rh * 8 + (l >> 2);
            const __half* eRow = g_E + (n0 + nloc) * HDIM + wn * 64 + 2 * (l & 3);
            float s = 0.0f;
            #pragma unroll
            for (int nt = 0; nt < 8; nt++) {
                const float2 ef = __half22float2(*(const __half2*)(eRow + nt * 8));
                s += acc[mt][nt][rh * 2] * ef.x + acc[mt][nt][rh * 2 + 1] * ef.y;
            }
            s += __shfl_xor_sync(0xFFFFFFFF, s, 1);
            s += __shfl_xor_sync(0xFFFFFFFF, s, 2);
            rowsum[mt][rh] = s;
        }

    __syncthreads();                 // tiles dead; reuse smem as reducer
    float* red = (float*)smem;       // [2 wn][128 n] = 1 KB
    if ((l & 3) == 0) {
        #pragma unroll
        for (int mt = 0; mt < 2; mt++)
            #pragma unroll
            for (int rh = 0; rh < 2; rh++) {
                const int nloc = wm * 32 + mt * 16 + rh * 8 + (l >> 2);
                red[wn * 128 + nloc] = rowsum[mt][rh];
            }
    }
    __syncthreads();
    if (tid < 128)
        out[b * NPTS + n0 + tid] =
            (red[tid] + red[128 + tid]) * 6.103515625e-05f;  // 1/16384
}

// ---------------------------------------------------------------------------
extern "C" void kernel_launch(void* const* d_in, const int* in_sizes, int n_in,
                              void* d_out, int out_size)
{
    const float* act   = (const float*)d_in[0];   // [8,128,128]
    const float* mu    = (const float*)d_in[1];   // [4096,2]
    const float* sigma = (const float*)d_in[2];   // [4096,2]
    float* out = (float*)d_out;                   // [8,64,64]

    cudaFuncSetAttribute(corr_mma_kernel,
                         cudaFuncAttributeMaxDynamicSharedMemorySize, SMEM_REQ);

    prep_kernel<<<(NPTS * HDIM) / 256, 256>>>(act, mu, sigma);
    corr_mma_kernel<<<dim3(NPTS / 128, 8), 256, SMEM_REQ>>>(out);
}

// round 8
// speedup vs baseline: 1.1684x; 1.1684x over previous
#include <cuda_runtime.h>
#include <cuda_fp16.h>
#include <cstdint>

// Single fused kernel:
// corr[b,n] = (1/16384) * sum_h exp(-(gh-mux)^2/(2sx^2)) *
//                         ( sum_w exp(-(gw-muy)^2/(2sy^2)) * act[b,h,w] )
// Per CTA (n-tile 128, batch b):
//   - EwT tile   : computed in-CTA (fp16, smem)  [128n x 128w]
//   - act tile   : LDG fp32 -> half2 -> smem     [128h x 128w]
//   - GEMM       : mma.sync.m16n8k16.f16 (fp32 accum), M=128 N=128 K=128
//   - epilogue   : EhT computed on the fly in fp32, quad-shuffle + smem reduce

#define HDIM 128
#define NPTS 4096

__device__ __forceinline__ uint32_t smem_to_u32(const void* p) {
    uint32_t a;
    asm("{ .reg .u64 t; cvta.to.shared.u64 t, %1; cvt.u32.u64 %0, t; }" : "=r"(a) : "l"(p));
    return a;
}

#define LDSM_X4(r0, r1, r2, r3, addr)                                          \
    asm volatile("ldmatrix.sync.aligned.m8n8.x4.shared.b16 {%0,%1,%2,%3}, [%4];" \
        : "=r"(r0), "=r"(r1), "=r"(r2), "=r"(r3) : "r"(addr))

#define MMA_F16(c, a, b0, b1)                                                  \
    asm volatile("mma.sync.aligned.m16n8k16.row.col.f32.f16.f16.f32 "           \
        "{%0,%1,%2,%3},{%4,%5,%6,%7},{%8,%9},{%0,%1,%2,%3};"                    \
        : "+f"((c)[0]), "+f"((c)[1]), "+f"((c)[2]), "+f"((c)[3])                \
        : "r"((a)[0]), "r"((a)[1]), "r"((a)[2]), "r"((a)[3]), "r"(b0), "r"(b1))

// Rows padded to 272B = 17*16 -> ldmatrix lane addrs conflict-free.
#define NSTRIDE 272
#define TAB_BYTES (128 * NSTRIDE)                 // 34816
#define MUX_OFF   (2 * TAB_BYTES)                 // fp32 mu.x cache  [128]
#define INVX_OFF  (MUX_OFF + 512)                 // fp32 1/(2 sx^2)  [128]
#define SMEM_REQ  (INVX_OFF + 512)                // 70656

__global__ __launch_bounds__(256) void fused_kernel(
    const float* __restrict__ act,    // [8,128,128]
    const float* __restrict__ mu,     // [4096,2]
    const float* __restrict__ sigma,  // [4096,2]
    float* __restrict__ out)          // [8,4096]
{
    extern __shared__ char smem[];
    const uint32_t sbase = smem_to_u32(smem);
    const uint32_t sA = sbase;                  // EwT [n][w] fp16
    const uint32_t sB = sbase + TAB_BYTES;      // act [h][w] fp16

    const int tid = threadIdx.x;
    const int wid = tid >> 5, l = tid & 31;
    const int wm = wid & 3, wn = wid >> 2;
    const int b  = blockIdx.y;
    const int n0 = blockIdx.x * 128;

    // ---- Stage 1a: act[b] fp32 -> fp16 smem (LDG float4, STS 8B) ----------
    const float4* gact = (const float4*)(act + b * HDIM * HDIM);
    #pragma unroll
    for (int k = 0; k < 16; k++) {
        const int i = tid + k * 256;            // 0..4095 float4s
        const int r = i >> 5, q = i & 31;       // row, float4-in-row
        const float4 v = __ldg(&gact[i]);
        __half2* dst = (__half2*)(smem + TAB_BYTES + r * NSTRIDE + q * 8);
        dst[0] = __floats2half2_rn(v.x, v.y);
        dst[1] = __floats2half2_rn(v.z, v.w);
    }

    // ---- Stage 1b: mu.x / 1/(2 sx^2) cache for the epilogue ---------------
    if (tid < 128) {
        const float2 m = ((const float2*)mu)[n0 + tid];
        const float2 s = ((const float2*)sigma)[n0 + tid];
        *(float*)(smem + MUX_OFF + tid * 4)  = m.x;
        *(float*)(smem + INVX_OFF + tid * 4) = 1.0f / (2.0f * s.x * s.x);
    }

    // ---- Stage 1c: EwT tile in-CTA (64 exps/thread) -----------------------
    {
        const int en  = tid >> 1;               // local n row 0..127
        const int ew0 = (tid & 1) * 64;         // w start
        const float2 m = ((const float2*)mu)[n0 + en];
        const float2 s = ((const float2*)sigma)[n0 + en];
        const float invw = 1.0f / (2.0f * s.y * s.y);
        char* row = smem + en * NSTRIDE + ew0 * 2;
        #pragma unroll
        for (int w4 = 0; w4 < 16; w4++) {
            float e[4];
            #pragma unroll
            for (int j = 0; j < 4; j++) {
                const float d = (float)(ew0 + w4 * 4 + j) * (1.0f / 128.0f) - m.y;
                e[j] = __expf(-(d * d * invw));
            }
            __half2* dst = (__half2*)(row + w4 * 8);
            dst[0] = __floats2half2_rn(e[0], e[1]);
            dst[1] = __floats2half2_rn(e[2], e[3]);
        }
    }
    __syncthreads();

    // ---- Stage 2: warp-mma GEMM ------------------------------------------
    float acc[2][8][4];
    #pragma unroll
    for (int mt = 0; mt < 2; mt++)
        #pragma unroll
        for (int nt = 0; nt < 8; nt++)
            #pragma unroll
            for (int k = 0; k < 4; k++) acc[mt][nt][k] = 0.0f;

    const uint32_t lrow = l & 15, lcol = (l >> 4) * 16;
    const uint32_t aBase = sA + (wm * 32 + lrow) * NSTRIDE + lcol;
    const uint32_t bBase = sB + (wn * 64 + lrow) * NSTRIDE + lcol;

    #pragma unroll
    for (int ks = 0; ks < 8; ks++) {
        const uint32_t koff = ks * 32;
        uint32_t ah[2][4], bb[4][4];
        #pragma unroll
        for (int mt = 0; mt < 2; mt++)
            LDSM_X4(ah[mt][0], ah[mt][1], ah[mt][2], ah[mt][3],
                    aBase + mt * (16 * NSTRIDE) + koff);
        #pragma unroll
        for (int p = 0; p < 4; p++)
            LDSM_X4(bb[p][0], bb[p][1], bb[p][2], bb[p][3],
                    bBase + p * (16 * NSTRIDE) + koff);
        #pragma unroll
        for (int mt = 0; mt < 2; mt++)
            #pragma unroll
            for (int p = 0; p < 4; p++) {
                MMA_F16(acc[mt][2 * p],     ah[mt], bb[p][0], bb[p][2]);
                MMA_F16(acc[mt][2 * p + 1], ah[mt], bb[p][1], bb[p][3]);
            }
    }

    // ---- Stage 3: epilogue, EhT in fp32 on the fly ------------------------
    // Thread's D rows: nloc = wm*32 + mt*16 + rh*8 + l/4 (n)
    //          cols:   h    = wn*64 + nt*8 + 2(l&3) + {0,1}
    const float h0f = (float)(wn * 64 + 2 * (l & 3)) * (1.0f / 128.0f);
    float rowsum[2][2];
    #pragma unroll
    for (int mt = 0; mt < 2; mt++)
        #pragma unroll
        for (int rh = 0; rh < 2; rh++) {
            const int nloc = wm * 32 + mt * 16 + rh * 8 + (l >> 2);
            const float a   = *(const float*)(smem + MUX_OFF + nloc * 4);
            const float inv = *(const float*)(smem + INVX_OFF + nloc * 4);
            float s = 0.0f;
            #pragma unroll
            for (int nt = 0; nt < 8; nt++) {
                const float d0 = h0f + (float)nt * (8.0f / 128.0f) - a;
                const float d1 = d0 + (1.0f / 128.0f);
                const float e0 = __expf(-(d0 * d0 * inv));
                const float e1 = __expf(-(d1 * d1 * inv));
                s += acc[mt][nt][rh * 2] * e0 + acc[mt][nt][rh * 2 + 1] * e1;
            }
            s += __shfl_xor_sync(0xFFFFFFFF, s, 1);
            s += __shfl_xor_sync(0xFFFFFFFF, s, 2);
            rowsum[mt][rh] = s;
        }

    __syncthreads();                 // tiles dead; reuse smem as reducer
    float* red = (float*)smem;       // [2 wn][128 n] = 1 KB
    if ((l & 3) == 0) {
        #pragma unroll
        for (int mt = 0; mt < 2; mt++)
            #pragma unroll
            for (int rh = 0; rh < 2; rh++) {
                const int nloc = wm * 32 + mt * 16 + rh * 8 + (l >> 2);
                red[wn * 128 + nloc] = rowsum[mt][rh];
            }
    }
    __syncthreads();
    if (tid < 128)
        out[b * NPTS + n0 + tid] =
            (red[tid] + red[128 + tid]) * 6.103515625e-05f;  // 1/16384
}

// ---------------------------------------------------------------------------
extern "C" void kernel_launch(void* const* d_in, const int* in_sizes, int n_in,
                              void* d_out, int out_size)
{
    const float* act   = (const float*)d_in[0];   // [8,128,128]
    const float* mu    = (const float*)d_in[1];   // [4096,2]
    const float* sigma = (const float*)d_in[2];   // [4096,2]
    float* out = (float*)d_out;                   // [8,64,64]

    cudaFuncSetAttribute(fused_kernel,
                         cudaFuncAttributeMaxDynamicSharedMemorySize, SMEM_REQ);

    fused_kernel<<<dim3(NPTS / 128, 8), 256, SMEM_REQ>>>(act, mu, sigma, out);
}